// round 5
// baseline (speedup 1.0000x reference)
#include <cuda_runtime.h>
#include <math.h>

// Problem dims
#define S_ 2048
#define B_ 64
#define I_ 256
#define H_ 512
#define ROWS_ (S_ * B_)          // 131072
#define BH_ (B_ * H_)

// ---------------- scratch (no cudaMalloc allowed) ----------------
__device__ float g_buf0[(size_t)S_ * BH_];   // xb0 -> y0 (in place)
__device__ float g_buf1[(size_t)S_ * BH_];   // y1
__device__ unsigned g_ctr0[128];             // per-bgroup arrival counters (128B apart)
__device__ unsigned g_flag0[128];
__device__ unsigned g_ctr1[128];
__device__ unsigned g_flag1[128];

// ---------------- packed f32x2 FMA ----------------
__device__ __forceinline__ void fma2(float2& d, float2 a, float2 b) {
    asm volatile(
        "{\n\t"
        ".reg .b64 ra, rb, rd;\n\t"
        "mov.b64 ra, {%2, %3};\n\t"
        "mov.b64 rb, {%4, %5};\n\t"
        "mov.b64 rd, {%0, %1};\n\t"
        "fma.rn.f32x2 rd, ra, rb, rd;\n\t"
        "mov.b64 {%0, %1}, rd;\n\t"
        "}"
        : "+f"(d.x), "+f"(d.y)
        : "f"(a.x), "f"(a.y), "f"(b.x), "f"(b.y));
}
__device__ __forceinline__ void fma4(float2& acc, float4 a, float4 w) {
    fma2(acc, make_float2(a.x, a.y), make_float2(w.x, w.y));
    fma2(acc, make_float2(a.z, a.w), make_float2(w.z, w.w));
}

__device__ __forceinline__ unsigned su32(const void* p) {
    return (unsigned)__cvta_generic_to_shared(p);
}
__device__ __forceinline__ void cp16(unsigned dst, const float* src) {
    asm volatile("cp.async.cg.shared.global [%0], [%1], 16;" :: "r"(dst), "l"(src));
}
#define CP_COMMIT() asm volatile("cp.async.commit_group;" ::: "memory")
#define CP_WAIT0()  asm volatile("cp.async.wait_group 0;" ::: "memory")
#define CP_WAIT1()  asm volatile("cp.async.wait_group 1;" ::: "memory")

// ---------------- counter init (graph-replay safe reset) ----------------
__global__ void init_ctrs_kernel() {
    int i = threadIdx.x;
    g_ctr0[i] = 0u; g_flag0[i] = 0u;
    g_ctr1[i] = 0u; g_flag1[i] = 0u;
}

// ---------------- projection GEMM (layer 0 only) ----------------
#define TM 64
#define TN 64
#define KC 64
#define SAST 66

__global__ void __launch_bounds__(256) proj_kernel(
    const float* __restrict__ A,
    const float* __restrict__ W,
    const int*   __restrict__ Wmask,
    const float* __restrict__ bias1,
    const float* __restrict__ bias2,
    int K)
{
    __shared__ float SA[TM * SAST];
    __shared__ float SW[TN * SAST];

    float* C = g_buf0;
    const int m0 = blockIdx.x * TM;
    const int n0 = blockIdx.y * TN;
    const int tid = threadIdx.x;
    const int tx = tid & 15;
    const int ty = tid >> 4;

    float2 acc[4][4];
#pragma unroll
    for (int i = 0; i < 4; i++)
#pragma unroll
        for (int j = 0; j < 4; j++) acc[i][j] = make_float2(0.f, 0.f);

    for (int kc = 0; kc < K; kc += KC) {
#pragma unroll
        for (int t = tid; t < TM * 16; t += 256) {
            int r = t >> 4, q = t & 15;
            float4 v = *(const float4*)&A[(size_t)(m0 + r) * K + kc + 4 * q];
            int o = r * SAST + 4 * q;
            *(float2*)&SA[o]     = make_float2(v.x, v.y);
            *(float2*)&SA[o + 2] = make_float2(v.z, v.w);
        }
#pragma unroll
        for (int t = tid; t < TN * 16; t += 256) {
            int r = t >> 4, q = t & 15;
            size_t g = (size_t)(n0 + r) * K + kc + 4 * q;
            float4 v = *(const float4*)&W[g];
            int4  mm = *(const int4*)&Wmask[g];
            int o = r * SAST + 4 * q;
            SW[o]     = v.x * (float)mm.x;
            SW[o + 1] = v.y * (float)mm.y;
            SW[o + 2] = v.z * (float)mm.z;
            SW[o + 3] = v.w * (float)mm.w;
        }
        __syncthreads();

#pragma unroll 8
        for (int k = 0; k < KC; k += 2) {
            float2 a[4], w[4];
#pragma unroll
            for (int i = 0; i < 4; i++) a[i] = *(float2*)&SA[(ty + 16 * i) * SAST + k];
#pragma unroll
            for (int j = 0; j < 4; j++) w[j] = *(float2*)&SW[(tx + 16 * j) * SAST + k];
#pragma unroll
            for (int i = 0; i < 4; i++)
#pragma unroll
                for (int j = 0; j < 4; j++) fma2(acc[i][j], a[i], w[j]);
        }
        __syncthreads();
    }

#pragma unroll
    for (int j = 0; j < 4; j++) {
        int n = n0 + tx + 16 * j;
        float bb = bias1[n] + bias2[n];
#pragma unroll
        for (int i = 0; i < 4; i++) {
            int m = m0 + ty + 16 * i;
            C[(size_t)m * H_ + n] = acc[i][j].x + acc[i][j].y + bb;
        }
    }
}

// ---------------- fused 2-layer recurrence, software-pipelined -----------
// Grid step t: layer0 computes y0[t] (t<S), layer1 computes y1[t-2] (t>=2).
// 128 CTAs = 4 bg x 32 hg, 256 threads, weights in registers.
#define NCTA 128
#define RTH  256
#define GSZ  32
#define HST  520            // hs row stride (floats)
#define RST  272            // red ks stride, conflict-free STS.64 / LDS.32
#define RED_G (32 * RST)
#define HS0_OFF 0                       // double buffer [2][16][HST]
#define HS1_OFF (32 * HST)              // [16][HST]
#define RED_OFF (48 * HST)              // [3][32][RST]
#define SMEM_FLOATS (RED_OFF + 3 * RED_G)
#define RNN_SMEM_BYTES (SMEM_FLOATS * 4)   // 204,288 B

__device__ __forceinline__ void spin_ge(unsigned* flag, unsigned v) {
    if (threadIdx.x == 0) {
        unsigned f;
        do {
            asm volatile("ld.acquire.gpu.global.u32 %0, [%1];"
                         : "=r"(f) : "l"(flag) : "memory");
        } while (f < v);
    }
    __syncthreads();
}

__device__ __forceinline__ void arrive(unsigned* ctr, unsigned* flag, unsigned round) {
    if (threadIdx.x == 0) {
        unsigned old;
        asm volatile("atom.acq_rel.gpu.global.add.u32 %0, [%1], 1;"
                     : "=r"(old) : "l"(ctr) : "memory");
        if (old == round * GSZ - 1) {
            asm volatile("st.release.gpu.global.u32 [%0], %1;"
                         :: "l"(flag), "r"(round) : "memory");
        }
    }
}

__global__ void __launch_bounds__(RTH, 1) rnn_pipe_kernel(
    const float* __restrict__ Whh0, const int* __restrict__ m_hh0,
    const float* __restrict__ Wih1, const int* __restrict__ m_ih1,
    const float* __restrict__ Whh1, const int* __restrict__ m_hh1,
    const float* __restrict__ b_ih1, const float* __restrict__ b_hh1)
{
    extern __shared__ float smem[];
    float* hs0 = smem + HS0_OFF;     // [2][16][HST]
    float* hs1 = smem + HS1_OFF;     // [16][HST]
    float* red = smem + RED_OFF;     // [3][32][RST]

    const int bg = blockIdx.x >> 5;
    const int hg = blockIdx.x & 31;
    const int b0 = bg * 16;
    const int h0 = hg * 16;
    const int tid = threadIdx.x;
    const int tx = tid & 7;           // col pair
    const int ks = tid >> 3;          // 0..31, k-slice of 16
    const int k0 = ks * 16;

    unsigned* ctr0  = &g_ctr0[bg * GSZ];
    unsigned* flag0 = &g_flag0[bg * GSZ];
    unsigned* ctr1  = &g_ctr1[bg * GSZ];
    unsigned* flag1 = &g_flag1[bg * GSZ];

    // zero hs1 (y1[-1] = 0 for the first layer-1 step)
    for (int i = tid; i < 16 * HST; i += RTH) hs1[i] = 0.f;

    // ---- permanent register weights ----
    float4 wr[3][2][4];
    {
        const float* Wp[3] = { Whh0, Wih1, Whh1 };
        const int*   Mp[3] = { m_hh0, m_ih1, m_hh1 };
#pragma unroll
        for (int g = 0; g < 3; g++)
#pragma unroll
            for (int c = 0; c < 2; c++) {
                size_t ro = (size_t)(h0 + 2 * tx + c) * H_ + k0;
#pragma unroll
                for (int q = 0; q < 4; q++) {
                    float4 v = *(const float4*)&Wp[g][ro + 4 * q];
                    int4  mm = *(const int4*)&Mp[g][ro + 4 * q];
                    wr[g][c][q] = make_float4(v.x * (float)mm.x, v.y * (float)mm.y,
                                              v.z * (float)mm.z, v.w * (float)mm.w);
                }
            }
    }

    const int orow = tid >> 4;
    const int ocol = tid & 15;
    const size_t offO = (size_t)(b0 + orow) * H_ + (h0 + ocol);
    const float bL1 = __ldg(&b_ih1[h0 + ocol]) + __ldg(&b_hh1[h0 + ocol]);
    float xv = __ldg(&g_buf0[offO]);

    const unsigned hs0_b = su32(hs0);
    const unsigned hs1_b = su32(hs1);
    const int sts0 = 0 * RED_G + ks * RST + 2 * tx;
    const int sts1 = 1 * RED_G + ks * RST + 2 * tx;
    const int sts2 = 2 * RED_G + ks * RST + 2 * tx;
    __syncthreads();   // hs1 zeros visible

    for (int t = 0; t <= S_ + 1; ++t) {
        // ---- P0: stage hs0[t&1] <- y0[t-1] ----
        if (t >= 1 && t <= S_) {
            spin_ge(flag0, (unsigned)t);
            const float* src = g_buf0 + (size_t)(t - 1) * BH_ + (size_t)b0 * H_;
            unsigned dstb = hs0_b + (unsigned)((t & 1) * 16 * HST) * 4u;
#pragma unroll
            for (int i = 0; i < 8; i++) {
                int idx = tid + i * RTH;             // 0..2047 16B chunks
                int r = idx >> 7, q = idx & 127;
                cp16(dstb + (unsigned)(r * HST + 4 * q) * 4u, src + (size_t)idx * 4);
            }
            CP_COMMIT();
        }

        // ---- PA: layer-1 step t-2 ----
        if (t >= 2) {
            if (t <= S_) { CP_WAIT1(); } else { CP_WAIT0(); }  // hs1 (old group) landed
            __syncthreads();
            const float* hA = hs0 + ((t - 1) & 1) * 16 * HST;   // y0[t-2]
#pragma unroll 4
            for (int r = 0; r < 16; r++) {
                const float* apA = &hA[r * HST + k0];
                const float* apB = &hs1[r * HST + k0];
                float4 a0 = *(const float4*)&apA[0];
                float4 a1 = *(const float4*)&apA[4];
                float4 a2 = *(const float4*)&apA[8];
                float4 a3 = *(const float4*)&apA[12];
                float4 e0 = *(const float4*)&apB[0];
                float4 e1 = *(const float4*)&apB[4];
                float4 e2 = *(const float4*)&apB[8];
                float4 e3 = *(const float4*)&apB[12];
                float2 p10 = make_float2(0.f, 0.f), p11 = make_float2(0.f, 0.f);
                float2 p20 = make_float2(0.f, 0.f), p21 = make_float2(0.f, 0.f);
                fma4(p10, a0, wr[1][0][0]); fma4(p11, a0, wr[1][1][0]);
                fma4(p20, e0, wr[2][0][0]); fma4(p21, e0, wr[2][1][0]);
                fma4(p10, a1, wr[1][0][1]); fma4(p11, a1, wr[1][1][1]);
                fma4(p20, e1, wr[2][0][1]); fma4(p21, e1, wr[2][1][1]);
                fma4(p10, a2, wr[1][0][2]); fma4(p11, a2, wr[1][1][2]);
                fma4(p20, e2, wr[2][0][2]); fma4(p21, e2, wr[2][1][2]);
                fma4(p10, a3, wr[1][0][3]); fma4(p11, a3, wr[1][1][3]);
                fma4(p20, e3, wr[2][0][3]); fma4(p21, e3, wr[2][1][3]);
                *(float2*)&red[sts1 + r * 16] =
                    make_float2(p10.x + p10.y, p11.x + p11.y);
                *(float2*)&red[sts2 + r * 16] =
                    make_float2(p20.x + p20.y, p21.x + p21.y);
            }
            __syncthreads();
            float s1 = 0.f, s2 = 0.f;
#pragma unroll
            for (int k = 0; k < 32; k++) {
                s1 += red[1 * RED_G + k * RST + tid];
                s2 += red[2 * RED_G + k * RST + tid];
            }
            g_buf1[(size_t)(t - 2) * BH_ + offO] = tanhf(s1 + s2 + bL1);
            arrive(ctr1, flag1, (unsigned)(t - 1));
        }

        // ---- PC: layer-0 step t ----
        if (t < S_) {
            float s0 = 0.f;
            if (t >= 1) {
                CP_WAIT0();          // hs0[t&1] landed
                __syncthreads();
                const float* hC = hs0 + (t & 1) * 16 * HST;
#pragma unroll 4
                for (int r = 0; r < 16; r++) {
                    const float* ap = &hC[r * HST + k0];
                    float4 a0 = *(const float4*)&ap[0];
                    float4 a1 = *(const float4*)&ap[4];
                    float4 a2 = *(const float4*)&ap[8];
                    float4 a3 = *(const float4*)&ap[12];
                    float2 p00 = make_float2(0.f, 0.f), p01 = make_float2(0.f, 0.f);
                    fma4(p00, a0, wr[0][0][0]); fma4(p01, a0, wr[0][1][0]);
                    fma4(p00, a1, wr[0][0][1]); fma4(p01, a1, wr[0][1][1]);
                    fma4(p00, a2, wr[0][0][2]); fma4(p01, a2, wr[0][1][2]);
                    fma4(p00, a3, wr[0][0][3]); fma4(p01, a3, wr[0][1][3]);
                    *(float2*)&red[sts0 + r * 16] =
                        make_float2(p00.x + p00.y, p01.x + p01.y);
                }
                __syncthreads();
#pragma unroll
                for (int k = 0; k < 32; k++)
                    s0 += red[0 * RED_G + k * RST + tid];
            }
            g_buf0[(size_t)t * BH_ + offO] = tanhf(s0 + xv);
            if (t + 1 < S_)
                xv = __ldg(&g_buf0[(size_t)(t + 1) * BH_ + offO]);
            arrive(ctr0, flag0, (unsigned)(t + 1));
        }

        // ---- stage hs1 <- y1[t-2] for next iteration's PA ----
        if (t >= 2 && t <= S_) {
            spin_ge(flag1, (unsigned)(t - 1));
            const float* src = g_buf1 + (size_t)(t - 2) * BH_ + (size_t)b0 * H_;
#pragma unroll
            for (int i = 0; i < 8; i++) {
                int idx = tid + i * RTH;
                int r = idx >> 7, q = idx & 127;
                cp16(hs1_b + (unsigned)(r * HST + 4 * q) * 4u, src + (size_t)idx * 4);
            }
            CP_COMMIT();
        }
    }
}

// ---------------- final copy ----------------
__global__ void copy_out_kernel(float* __restrict__ dst) {
    int i = blockIdx.x * blockDim.x + threadIdx.x;
    dst[i] = g_buf1[(size_t)(S_ - 1) * BH_ + i];
}

// ---------------- launch ----------------
extern "C" void kernel_launch(void* const* d_in, const int* in_sizes, int n_in,
                              void* d_out, int out_size) {
    const float* x       = (const float*)d_in[0];
    const float* W_ih0   = (const float*)d_in[1];
    const float* W_hh0   = (const float*)d_in[2];
    const float* b_ih0   = (const float*)d_in[3];
    const float* b_hh0   = (const float*)d_in[4];
    const float* W_ih1   = (const float*)d_in[5];
    const float* W_hh1   = (const float*)d_in[6];
    const float* b_ih1   = (const float*)d_in[7];
    const float* b_hh1   = (const float*)d_in[8];
    const int*   m_ih0   = (const int*)d_in[9];
    const int*   m_hh0   = (const int*)d_in[10];
    const int*   m_ih1   = (const int*)d_in[11];
    const int*   m_hh1   = (const int*)d_in[12];
    float* out = (float*)d_out;

    static bool attr_set = false;
    if (!attr_set) {
        cudaFuncSetAttribute(rnn_pipe_kernel,
                             cudaFuncAttributeMaxDynamicSharedMemorySize,
                             RNN_SMEM_BYTES);
        attr_set = true;
    }

    init_ctrs_kernel<<<1, 128>>>();

    dim3 pgrid(ROWS_ / TM, H_ / TN);
    proj_kernel<<<pgrid, 256>>>(x, W_ih0, m_ih0, b_ih0, b_hh0, I_);

    rnn_pipe_kernel<<<NCTA, RTH, RNN_SMEM_BYTES>>>(
        W_hh0, m_hh0, W_ih1, m_ih1, W_hh1, m_hh1, b_ih1, b_hh1);

    copy_out_kernel<<<(BH_) / 256, 256>>>(out);
}